// round 5
// baseline (speedup 1.0000x reference)
#include <cuda_runtime.h>

#define NROWS 65536
#define ZD    256
#define KCODES 1024
#define BM 128
#define BN 128
#define BK 16
#define LDA 132              // padded smem stride
#define NBLK (NROWS / BM)    // 512

#define ZQ_ELEMS ((size_t)NROWS * ZD)
#define IDX_OFF  ZQ_ELEMS
#define LOSS_OFF (ZQ_ELEMS + (size_t)NROWS)

typedef unsigned long long ull;

__device__ float g_enorm[KCODES];
__device__ float g_znorm[NROWS];
__device__ float g_partial[NBLK];

// ---- packed fp32x2 helpers (sm_100+); each half rounds exactly like scalar FFMA ----
__device__ __forceinline__ ull pack2(float lo, float hi) {
    ull r; asm("mov.b64 %0, {%1, %2};" : "=l"(r) : "f"(lo), "f"(hi)); return r;
}
__device__ __forceinline__ void unpack2(float& lo, float& hi, ull v) {
    asm("mov.b64 {%0, %1}, %2;" : "=f"(lo), "=f"(hi) : "l"(v));
}
__device__ __forceinline__ ull ffma2(ull a, ull b, ull c) {
    ull d; asm("fma.rn.f32x2 %0, %1, %2, %3;" : "=l"(d) : "l"(a), "l"(b), "l"(c)); return d;
}

// ================= K1: sum-of-squares per row, emulating XLA's GPU row-reduce tree =====
// Virtual thread t holds fl(x[2t]^2 + x[2t+1]^2); shfl_down strides 16..1 within each
// 32-lane group; the 4 group partials combine as (p0+p2)+(p1+p3). One real warp per row.
// Destination selected INSIDE device code (mode 0 -> g_znorm, 1 -> g_enorm): passing a
// __device__ symbol as a host-side kernel argument passes the host shadow address (the
// bug behind the 128 MiB rule violations in rounds 1-3).
__global__ void sqsum_tree_kernel(const float* __restrict__ src, int nrows, int mode)
{
    int row = blockIdx.x * 8 + (threadIdx.x >> 5);
    if (row >= nrows) return;
    int lane = threadIdx.x & 31;
    const float2* p = (const float2*)(src + (size_t)row * ZD);

    float acc[4];
#pragma unroll
    for (int j = 0; j < 4; j++) {
        float2 v = p[lane + 32 * j];
        float a = __fmul_rn(v.x, v.x);
        float b = __fmul_rn(v.y, v.y);
        acc[j] = __fadd_rn(a, b);
    }
#pragma unroll
    for (int off = 16; off; off >>= 1) {
#pragma unroll
        for (int j = 0; j < 4; j++)
            acc[j] = __fadd_rn(acc[j], __shfl_down_sync(0xffffffffu, acc[j], off));
    }
    if (lane == 0) {
        float l = __fadd_rn(acc[0], acc[2]);
        float r = __fadd_rn(acc[1], acc[3]);
        float s = __fadd_rn(l, r);
        if (mode == 0) g_znorm[row] = s;
        else           g_enorm[row] = s;
    }
}

// ================= K2: fused GEMM + quantized-score argmin + gather + loss =============
// Mainloop structure identical to the round-0 submission (verified clean launch);
// z-norms live in SMEM so the score phase adds no sustained register pressure.
__global__ __launch_bounds__(256, 2) void vq_main(
    const float* __restrict__ Z, const float* __restrict__ E, float* __restrict__ out)
{
    __shared__ __align__(16) float As[BK * LDA];
    __shared__ __align__(16) float Bs[BK * LDA];
    __shared__ float sZn[BM];
    __shared__ float sBestV[BM];
    __shared__ int   sBestI[BM];
    __shared__ float sRed[8];

    const int tid = threadIdx.x;
    const int tx = tid & 15;       // code micro-tile coordinate
    const int ty = tid >> 4;       // row micro-tile coordinate
    const int row0 = blockIdx.x * BM;

    if (tid < BM) {
        sBestV[tid] = 3.402823466e38f;
        sBestI[tid] = 0;
        sZn[tid] = g_znorm[row0 + tid];
    }
    // first __syncthreads inside the k0 loop orders these writes before any read

    const float* Ablk = Z + (size_t)row0 * ZD;

    const int q0 = tid, q1 = tid + 256;
    const int m0 = q0 >> 2, c40 = (q0 & 3) * 4;
    const int m1 = q1 >> 2, c41 = (q1 & 3) * 4;

    for (int ct = 0; ct < KCODES; ct += BN) {
        ull acc[4][8];   // [row-pair][code]  (rows paired in the f32x2 lanes)
#pragma unroll
        for (int i = 0; i < 4; i++)
#pragma unroll
            for (int j = 0; j < 8; j++) acc[i][j] = 0ull;

        const float* Bblk = E + (size_t)ct * ZD;

        for (int k0 = 0; k0 < ZD; k0 += BK) {   // k strictly ascending (serial order)
            float4 a0 = *(const float4*)(Ablk + (size_t)m0 * ZD + k0 + c40);
            float4 a1 = *(const float4*)(Ablk + (size_t)m1 * ZD + k0 + c41);
            float4 b0 = *(const float4*)(Bblk + (size_t)m0 * ZD + k0 + c40);
            float4 b1 = *(const float4*)(Bblk + (size_t)m1 * ZD + k0 + c41);
            __syncthreads();   // protect smem from previous chunk's readers
            As[(c40 + 0) * LDA + m0] = a0.x; As[(c40 + 1) * LDA + m0] = a0.y;
            As[(c40 + 2) * LDA + m0] = a0.z; As[(c40 + 3) * LDA + m0] = a0.w;
            As[(c41 + 0) * LDA + m1] = a1.x; As[(c41 + 1) * LDA + m1] = a1.y;
            As[(c41 + 2) * LDA + m1] = a1.z; As[(c41 + 3) * LDA + m1] = a1.w;
            Bs[(c40 + 0) * LDA + m0] = b0.x; Bs[(c40 + 1) * LDA + m0] = b0.y;
            Bs[(c40 + 2) * LDA + m0] = b0.z; Bs[(c40 + 3) * LDA + m0] = b0.w;
            Bs[(c41 + 0) * LDA + m1] = b1.x; Bs[(c41 + 1) * LDA + m1] = b1.y;
            Bs[(c41 + 2) * LDA + m1] = b1.z; Bs[(c41 + 3) * LDA + m1] = b1.w;
            __syncthreads();
#pragma unroll
            for (int kk = 0; kk < BK; kk++) {
                const float* ar = As + kk * LDA + ty * 8;
                ulonglong2 t0 = *(const ulonglong2*)(ar);
                ulonglong2 t1 = *(const ulonglong2*)(ar + 4);
                ull a2[4] = { t0.x, t0.y, t1.x, t1.y };
                const float* br = Bs + kk * LDA + tx * 8;
                float4 bq0 = *(const float4*)(br);
                float4 bq1 = *(const float4*)(br + 4);
                ull b2[8];
                b2[0] = pack2(bq0.x, bq0.x); b2[1] = pack2(bq0.y, bq0.y);
                b2[2] = pack2(bq0.z, bq0.z); b2[3] = pack2(bq0.w, bq0.w);
                b2[4] = pack2(bq1.x, bq1.x); b2[5] = pack2(bq1.y, bq1.y);
                b2[6] = pack2(bq1.z, bq1.z); b2[7] = pack2(bq1.w, bq1.w);
#pragma unroll
                for (int j = 0; j < 8; j++)
#pragma unroll
                    for (int i = 0; i < 4; i++)
                        acc[i][j] = ffma2(a2[i], b2[j], acc[i][j]);
            }
        }

        // ---- reference-exact scores: s = fl(fl(zn+en) - 2*dot); argmin, first-index ties ----
        float v[8]; int vi[8];
#pragma unroll
        for (int r = 0; r < 8; r++) { v[r] = 3.402823466e38f; vi[r] = 0; }
#pragma unroll
        for (int j = 0; j < 8; j++) {
            int c = ct + tx * 8 + j;
            float en = g_enorm[c];
#pragma unroll
            for (int i = 0; i < 4; i++) {
                float lo, hi; unpack2(lo, hi, acc[i][j]);
                float tLo = __fadd_rn(sZn[ty * 8 + 2 * i], en);       // transient LDS
                float tHi = __fadd_rn(sZn[ty * 8 + 2 * i + 1], en);
                float sLo = __fmaf_rn(-2.0f, lo, tLo);  // == fl(t - fl(2*dot)); 2*dot exact
                float sHi = __fmaf_rn(-2.0f, hi, tHi);
                if (sLo < v[2 * i])     { v[2 * i] = sLo;     vi[2 * i] = c; }
                if (sHi < v[2 * i + 1]) { v[2 * i + 1] = sHi; vi[2 * i + 1] = c; }
            }
        }
#pragma unroll
        for (int r = 0; r < 8; r++) {
            float mv = v[r]; int mi = vi[r];
#pragma unroll
            for (int o = 8; o; o >>= 1) {
                float ov = __shfl_xor_sync(0xffffffffu, mv, o);
                int   oi = __shfl_xor_sync(0xffffffffu, mi, o);
                if (ov < mv || (ov == mv && oi < mi)) { mv = ov; mi = oi; }
            }
            if (tx == 0) {
                int rr = ty * 8 + r;
                if (mv < sBestV[rr] || (mv == sBestV[rr] && mi < sBestI[rr])) {
                    sBestV[rr] = mv; sBestI[rr] = mi;
                }
            }
        }
    }
    __syncthreads();

    // ---- gather z_q; z_q_st = fl(z + fl(z_q - z)) exactly as reference; loss partial ----
    float lsum = 0.0f;
    for (int e = tid; e < BM * (ZD / 4); e += 256) {
        int m = e >> 6;
        int c4 = (e & 63) * 4;
        int idx = sBestI[m];
        float4 q  = *(const float4*)(E + (size_t)idx * ZD + c4);
        float4 z4 = *(const float4*)(Ablk + (size_t)m * ZD + c4);
        float d0 = __fadd_rn(q.x, -z4.x), d1 = __fadd_rn(q.y, -z4.y);
        float d2 = __fadd_rn(q.z, -z4.z), d3 = __fadd_rn(q.w, -z4.w);
        float4 o;
        o.x = __fadd_rn(z4.x, d0); o.y = __fadd_rn(z4.y, d1);
        o.z = __fadd_rn(z4.z, d2); o.w = __fadd_rn(z4.w, d3);
        lsum += d0 * d0 + d1 * d1 + d2 * d2 + d3 * d3;
        *(float4*)(out + (size_t)(row0 + m) * ZD + c4) = o;
    }
    if (tid < BM) out[IDX_OFF + row0 + tid] = (float)sBestI[tid];

#pragma unroll
    for (int o = 16; o; o >>= 1) lsum += __shfl_xor_sync(0xffffffffu, lsum, o);
    if ((tid & 31) == 0) sRed[tid >> 5] = lsum;
    __syncthreads();
    if (tid < 8) {
        float x = sRed[tid];
        x += __shfl_xor_sync(0xffu, x, 4);
        x += __shfl_xor_sync(0xffu, x, 2);
        x += __shfl_xor_sync(0xffu, x, 1);
        if (tid == 0) g_partial[blockIdx.x] = x;
    }
}

// ================= K3: deterministic final loss reduction =================
__global__ void finalize_kernel(float* __restrict__ out) {
    __shared__ float s[16];
    int t = threadIdx.x;
    float v = g_partial[t];
#pragma unroll
    for (int o = 16; o; o >>= 1) v += __shfl_xor_sync(0xffffffffu, v, o);
    if ((t & 31) == 0) s[t >> 5] = v;
    __syncthreads();
    if (t < 16) {
        float x = s[t];
        x += __shfl_xor_sync(0xffffu, x, 8);
        x += __shfl_xor_sync(0xffffu, x, 4);
        x += __shfl_xor_sync(0xffffu, x, 2);
        x += __shfl_xor_sync(0xffffu, x, 1);
        if (t == 0) {
            float mean = x / (float)((size_t)NROWS * ZD);
            out[LOSS_OFF] = mean + 0.25f * mean;   // (1 + BETA) * mean((z_q - z)^2)
        }
    }
}

extern "C" void kernel_launch(void* const* d_in, const int* in_sizes, int n_in,
                              void* d_out, int out_size) {
    const float* Z = (const float*)d_in[0];
    const float* E = (const float*)d_in[1];
    if (n_in >= 2 && in_sizes[0] < in_sizes[1]) { const float* t = Z; Z = E; E = t; }
    float* out = (float*)d_out;

    sqsum_tree_kernel<<<(NROWS + 7) / 8, 256>>>(Z, NROWS, 0);   // -> g_znorm
    sqsum_tree_kernel<<<(KCODES + 7) / 8, 256>>>(E, KCODES, 1); // -> g_enorm
    vq_main<<<NBLK, 256>>>(Z, E, out);
    finalize_kernel<<<1, 512>>>(out);
}